// round 1
// baseline (speedup 1.0000x reference)
#include <cuda_runtime.h>
#include <math.h>

#define N_NODES 100000
#define N_EDGES 600000
#define HID 256

// ---------------- scratch (device globals; no allocation allowed) ----------
__device__ float g_h  [(size_t)N_NODES * HID];   // post-GEMM features
__device__ float g_agg[(size_t)N_NODES * HID];   // aggregation target
__device__ float g_x  [(size_t)N_NODES * HID];   // next-layer input
__device__ float g_deg [N_NODES];
__device__ float g_dinv[N_NODES];
__device__ float g_norm[N_EDGES];
__device__ int   g_ei  [2 * N_EDGES];            // [0,E) = src, [E,2E) = dst
__device__ int   g_is64;

// ---------------- dtype probe: int64 vs int32 edge_index -------------------
// For int64 node ids < 2^17 the high 32-bit word of every element is 0.
// For int32 data, words at odd positions are random node ids; all-zero over
// 1024 samples has probability ~(1e-5)^1024.
__global__ void probe_kernel(const unsigned int* __restrict__ words) {
    __shared__ int nz;
    if (threadIdx.x == 0) nz = 0;
    __syncthreads();
    int local = 0;
    for (int i = threadIdx.x; i < 1024; i += blockDim.x)
        if (words[2 * i + 1] != 0u) local = 1;
    if (local) atomicOr(&nz, 1);
    __syncthreads();
    if (threadIdx.x == 0) g_is64 = (nz == 0) ? 1 : 0;
}

__global__ void convert_edges_kernel(const void* __restrict__ ei) {
    int i = blockIdx.x * blockDim.x + threadIdx.x;
    if (i >= 2 * N_EDGES) return;
    if (g_is64)
        g_ei[i] = (int)((const long long*)ei)[i];
    else
        g_ei[i] = ((const int*)ei)[i];
}

// ---------------- degree / norm --------------------------------------------
__global__ void zero_deg_kernel() {
    int i = blockIdx.x * blockDim.x + threadIdx.x;
    if (i < N_NODES) g_deg[i] = 0.0f;
}

__global__ void deg_count_kernel() {
    int e = blockIdx.x * blockDim.x + threadIdx.x;
    if (e < N_EDGES) atomicAdd(&g_deg[g_ei[N_EDGES + e]], 1.0f);
}

__global__ void dinv_kernel() {
    int i = blockIdx.x * blockDim.x + threadIdx.x;
    if (i < N_NODES) {
        float d = g_deg[i];
        g_dinv[i] = (d > 0.0f) ? rsqrtf(d) : 0.0f;
    }
}

__global__ void norm_kernel() {
    int e = blockIdx.x * blockDim.x + threadIdx.x;
    if (e < N_EDGES)
        g_norm[e] = g_dinv[g_ei[e]] * g_dinv[g_ei[N_EDGES + e]];
}

// ---------------- zero agg ---------------------------------------------------
__global__ void zero_agg_kernel() {
    int i = blockIdx.x * blockDim.x + threadIdx.x;   // over N*HID/4 float4
    if (i < N_NODES * (HID / 4))
        ((float4*)g_agg)[i] = make_float4(0.f, 0.f, 0.f, 0.f);
}

// ---------------- SGEMM: C[g_h] = A (MxK) * W (Kx256) ----------------------
// BM=128, BN=128, BK=8, TM=TN=8, 256 threads.
__global__ void sgemm_kernel(const float* __restrict__ Aext, int use_gx,
                             const float* __restrict__ W, int M, int K) {
    const float* __restrict__ A = use_gx ? g_x : Aext;
    __shared__ float As[8][128];
    __shared__ float Ws[8][128];
    const int tid = threadIdx.x;
    const int tx = tid & 15;        // 0..15 -> 8 cols each
    const int ty = tid >> 4;        // 0..15 -> 8 rows each
    const int blockM = blockIdx.x * 128;
    const int blockN = blockIdx.y * 128;

    const int aRow = tid >> 1;          // 0..127
    const int aCol = (tid & 1) * 4;     // 0 / 4
    const int wRow = tid >> 5;          // 0..7
    const int wCol = (tid & 31) * 4;    // 0..124

    float acc[8][8];
#pragma unroll
    for (int i = 0; i < 8; i++)
#pragma unroll
        for (int j = 0; j < 8; j++) acc[i][j] = 0.0f;

    for (int k0 = 0; k0 < K; k0 += 8) {
        float4 av = make_float4(0.f, 0.f, 0.f, 0.f);
        int row = blockM + aRow;
        if (row < M)
            av = *(const float4*)(A + (size_t)row * K + k0 + aCol);
        As[aCol + 0][aRow] = av.x;
        As[aCol + 1][aRow] = av.y;
        As[aCol + 2][aRow] = av.z;
        As[aCol + 3][aRow] = av.w;

        float4 wv = *(const float4*)(W + (size_t)(k0 + wRow) * HID + blockN + wCol);
        *(float4*)&Ws[wRow][wCol] = wv;
        __syncthreads();

#pragma unroll
        for (int k = 0; k < 8; k++) {
            float rm[8], rn[8];
            *(float4*)&rm[0] = *(const float4*)&As[k][ty * 8];
            *(float4*)&rm[4] = *(const float4*)&As[k][ty * 8 + 4];
            *(float4*)&rn[0] = *(const float4*)&Ws[k][tx * 8];
            *(float4*)&rn[4] = *(const float4*)&Ws[k][tx * 8 + 4];
#pragma unroll
            for (int i = 0; i < 8; i++)
#pragma unroll
                for (int j = 0; j < 8; j++)
                    acc[i][j] = fmaf(rm[i], rn[j], acc[i][j]);
        }
        __syncthreads();
    }

#pragma unroll
    for (int i = 0; i < 8; i++) {
        int row = blockM + ty * 8 + i;
        if (row < M) {
            float* crow = g_h + (size_t)row * HID + blockN + tx * 8;
            *(float4*)(crow + 0) = make_float4(acc[i][0], acc[i][1], acc[i][2], acc[i][3]);
            *(float4*)(crow + 4) = make_float4(acc[i][4], acc[i][5], acc[i][6], acc[i][7]);
        }
    }
}

// ---------------- scatter: g_agg[dst] += norm_e * g_h[src] -----------------
// 64 threads per edge, one float4 per thread (coalesced row read).
__global__ void scatter_kernel() {
    long long tid = (long long)blockIdx.x * blockDim.x + threadIdx.x;
    int e = (int)(tid >> 6);
    if (e >= N_EDGES) return;
    int c = (int)(tid & 63) << 2;
    int s = g_ei[e];
    int d = g_ei[N_EDGES + e];
    float nrm = g_norm[e];
    float4 v = *(const float4*)(g_h + (size_t)s * HID + c);
    float* p = g_agg + (size_t)d * HID + c;
    asm volatile("red.global.add.v4.f32 [%0], {%1,%2,%3,%4};"
                 :: "l"(p), "f"(v.x * nrm), "f"(v.y * nrm),
                    "f"(v.z * nrm), "f"(v.w * nrm)
                 : "memory");
}

// ---------------- epilogue: out = elu(agg + b) ------------------------------
__global__ void epilogue_kernel(const float* __restrict__ b,
                                float* __restrict__ extout, int use_ext) {
    int i = blockIdx.x * blockDim.x + threadIdx.x;   // over N*64 float4
    if (i >= N_NODES * (HID / 4)) return;
    int c = (i & 63) << 2;
    float4 v = ((const float4*)g_agg)[i];
    float4 bb = *(const float4*)(b + c);
    v.x += bb.x; v.y += bb.y; v.z += bb.z; v.w += bb.w;
    v.x = (v.x > 0.f) ? v.x : expm1f(v.x);
    v.y = (v.y > 0.f) ? v.y : expm1f(v.y);
    v.z = (v.z > 0.f) ? v.z : expm1f(v.z);
    v.w = (v.w > 0.f) ? v.w : expm1f(v.w);
    float* out = use_ext ? extout : g_x;
    ((float4*)out)[i] = v;
}

// ---------------- launch -----------------------------------------------------
extern "C" void kernel_launch(void* const* d_in, const int* in_sizes, int n_in,
                              void* d_out, int out_size) {
    const float* x  = (const float*)d_in[0];
    const void*  ei = d_in[1];
    const float* W1 = (const float*)d_in[2];
    const float* b1 = (const float*)d_in[3];
    const float* W2 = (const float*)d_in[4];
    const float* b2 = (const float*)d_in[5];
    const float* W3 = (const float*)d_in[6];
    const float* b3 = (const float*)d_in[7];
    float* out = (float*)d_out;

    const int TPB = 256;
    const int nodeBlocks = (N_NODES + TPB - 1) / TPB;
    const int edgeBlocks = (N_EDGES + TPB - 1) / TPB;
    const int ei2Blocks  = (2 * N_EDGES + TPB - 1) / TPB;
    const int featBlocks = (N_NODES * (HID / 4) + TPB - 1) / TPB;
    const long long scatterThreads = (long long)N_EDGES * 64;
    const int scatterBlocks = (int)((scatterThreads + TPB - 1) / TPB);

    // edge prep + normalization
    probe_kernel<<<1, 256>>>((const unsigned int*)ei);
    convert_edges_kernel<<<ei2Blocks, TPB>>>(ei);
    zero_deg_kernel<<<nodeBlocks, TPB>>>();
    deg_count_kernel<<<edgeBlocks, TPB>>>();
    dinv_kernel<<<nodeBlocks, TPB>>>();
    norm_kernel<<<edgeBlocks, TPB>>>();

    dim3 gemmGrid((N_NODES + 127) / 128, HID / 128);

    // layer 1: h = x @ W1 ; agg = scatter ; x' = elu(agg + b1)
    sgemm_kernel<<<gemmGrid, 256>>>(x, 0, W1, N_NODES, 64);
    zero_agg_kernel<<<featBlocks, TPB>>>();
    scatter_kernel<<<scatterBlocks, TPB>>>();
    epilogue_kernel<<<featBlocks, TPB>>>(b1, nullptr, 0);

    // layer 2
    sgemm_kernel<<<gemmGrid, 256>>>(nullptr, 1, W2, N_NODES, HID);
    zero_agg_kernel<<<featBlocks, TPB>>>();
    scatter_kernel<<<scatterBlocks, TPB>>>();
    epilogue_kernel<<<featBlocks, TPB>>>(b2, nullptr, 0);

    // layer 3 -> d_out
    sgemm_kernel<<<gemmGrid, 256>>>(nullptr, 1, W3, N_NODES, HID);
    zero_agg_kernel<<<featBlocks, TPB>>>();
    scatter_kernel<<<scatterBlocks, TPB>>>();
    epilogue_kernel<<<featBlocks, TPB>>>(b3, out, 1);
}

// round 2
// speedup vs baseline: 1.7056x; 1.7056x over previous
#include <cuda_runtime.h>
#include <math.h>
#include <stdint.h>

#define N_NODES 100000
#define N_EDGES 600000
#define HID 256
#define IN_CH 64

// ---------------- scratch (device globals; no allocation allowed) ----------
__device__ float g_h  [(size_t)N_NODES * HID];   // post-GEMM features
__device__ float g_agg[(size_t)N_NODES * HID];   // aggregation target
__device__ float g_x  [(size_t)N_NODES * HID];   // next-layer input
__device__ float g_aggx[(size_t)N_NODES * IN_CH];// layer-1 aggregated input
__device__ float g_deg [N_NODES];
__device__ float g_dinv[N_NODES];
__device__ float g_norm[N_EDGES];
__device__ int   g_ei  [2 * N_EDGES];            // [0,E) = src, [E,2E) = dst
__device__ int   g_is64;

// ---------------- dtype probe: int64 vs int32 edge_index -------------------
__global__ void probe_kernel(const unsigned int* __restrict__ words) {
    __shared__ int nz;
    if (threadIdx.x == 0) nz = 0;
    __syncthreads();
    int local = 0;
    for (int i = threadIdx.x; i < 1024; i += blockDim.x)
        if (words[2 * i + 1] != 0u) local = 1;
    if (local) atomicOr(&nz, 1);
    __syncthreads();
    if (threadIdx.x == 0) g_is64 = (nz == 0) ? 1 : 0;
}

__global__ void convert_edges_kernel(const void* __restrict__ ei) {
    int i = blockIdx.x * blockDim.x + threadIdx.x;
    if (i >= 2 * N_EDGES) return;
    if (g_is64)
        g_ei[i] = (int)((const long long*)ei)[i];
    else
        g_ei[i] = ((const int*)ei)[i];
}

// ---------------- degree / norm --------------------------------------------
__global__ void zero_deg_kernel() {
    int i = blockIdx.x * blockDim.x + threadIdx.x;
    if (i < N_NODES) g_deg[i] = 0.0f;
}

__global__ void deg_count_kernel() {
    int e = blockIdx.x * blockDim.x + threadIdx.x;
    if (e < N_EDGES) atomicAdd(&g_deg[g_ei[N_EDGES + e]], 1.0f);
}

__global__ void dinv_kernel() {
    int i = blockIdx.x * blockDim.x + threadIdx.x;
    if (i < N_NODES) {
        float d = g_deg[i];
        g_dinv[i] = (d > 0.0f) ? rsqrtf(d) : 0.0f;
    }
}

__global__ void norm_kernel() {
    int e = blockIdx.x * blockDim.x + threadIdx.x;
    if (e < N_EDGES)
        g_norm[e] = g_dinv[g_ei[e]] * g_dinv[g_ei[N_EDGES + e]];
}

// ---------------- zeroing ----------------------------------------------------
__global__ void zero_agg_kernel() {
    int i = blockIdx.x * blockDim.x + threadIdx.x;   // over N*HID/4 float4
    if (i < N_NODES * (HID / 4))
        ((float4*)g_agg)[i] = make_float4(0.f, 0.f, 0.f, 0.f);
}

__global__ void zero_aggx_kernel() {
    int i = blockIdx.x * blockDim.x + threadIdx.x;   // over N*IN_CH/4 float4
    if (i < N_NODES * (IN_CH / 4))
        ((float4*)g_aggx)[i] = make_float4(0.f, 0.f, 0.f, 0.f);
}

// ---------------- tf32 helpers ----------------------------------------------
__device__ __forceinline__ float to_tf32(float x) {
    uint32_t u;
    asm("cvt.rna.tf32.f32 %0, %1;" : "=r"(u) : "f"(x));
    return __uint_as_float(u);
}

__device__ __forceinline__ void mma_tf32(float c[4], const uint32_t a[4],
                                         uint32_t b0, uint32_t b1) {
    asm volatile(
        "mma.sync.aligned.m16n8k8.row.col.f32.tf32.tf32.f32 "
        "{%0,%1,%2,%3}, {%4,%5,%6,%7}, {%8,%9}, {%0,%1,%2,%3};"
        : "+f"(c[0]), "+f"(c[1]), "+f"(c[2]), "+f"(c[3])
        : "r"(a[0]), "r"(a[1]), "r"(a[2]), "r"(a[3]), "r"(b0), "r"(b1));
}

// ---------------- tf32 tensor GEMM: C[M,256] = A[M,K] @ W[K,256] ------------
// BM=64, BN=256 (full N per block -> A read once), BK=16, 8 warps (2m x 4n),
// warp tile 32x64 (m-atoms 2, n-atoms 8). do_act: C = elu(acc + bias).
// asel: 0 = ext A, 1 = g_aggx, 2 = g_x.  csel: 0 = ext C, 1 = g_h, 2 = g_x.
__global__ __launch_bounds__(256) void mma_gemm_kernel(
        const float* __restrict__ Aext, int asel,
        const float* __restrict__ W, const float* __restrict__ bias,
        float* __restrict__ Cext, int csel, int K, int do_act) {
    const float* __restrict__ A = (asel == 1) ? g_aggx : (asel == 2) ? g_x : Aext;
    float* __restrict__ C = (csel == 1) ? g_h : (csel == 2) ? g_x : Cext;
    const int M = N_NODES;

    __shared__ __align__(16) float As[16][72];
    __shared__ __align__(16) float Bs[16][264];

    const int tid  = threadIdx.x;
    const int lane = tid & 31;
    const int warp = tid >> 5;
    const int warpM = warp & 1;        // 0..1 -> 32-row group
    const int warpN = warp >> 1;       // 0..3 -> 64-col group
    const int gid = lane >> 2;         // 0..7
    const int lc  = lane & 3;          // 0..3

    const int blockM = blockIdx.x * 64;

    // A tile load map: 1 float4 per thread
    const int am = tid >> 2;           // 0..63
    const int ak = (tid & 3) * 4;      // 0,4,8,12
    // B tile load map: 4 float4 per thread
    const int brow0 = tid >> 6;        // 0..3 (+ 4*i)
    const int bcol  = (tid & 63) * 4;  // 0..252

    float acc[2][8][4];
#pragma unroll
    for (int i = 0; i < 2; i++)
#pragma unroll
        for (int j = 0; j < 8; j++)
#pragma unroll
            for (int v = 0; v < 4; v++) acc[i][j][v] = 0.0f;

    for (int k0 = 0; k0 < K; k0 += 16) {
        // ---- load A tile (guarded), transpose to As[k][m], tf32-round
        float4 av = make_float4(0.f, 0.f, 0.f, 0.f);
        int grow = blockM + am;
        if (grow < M)
            av = *(const float4*)(A + (size_t)grow * K + k0 + ak);
        As[ak + 0][am] = to_tf32(av.x);
        As[ak + 1][am] = to_tf32(av.y);
        As[ak + 2][am] = to_tf32(av.z);
        As[ak + 3][am] = to_tf32(av.w);

        // ---- load B tile (K multiple of 16, N=256 full width)
#pragma unroll
        for (int i = 0; i < 4; i++) {
            int row = brow0 + i * 4;
            float4 wv = *(const float4*)(W + (size_t)(k0 + row) * HID + bcol);
            float4 tv;
            tv.x = to_tf32(wv.x); tv.y = to_tf32(wv.y);
            tv.z = to_tf32(wv.z); tv.w = to_tf32(wv.w);
            *(float4*)&Bs[row][bcol] = tv;
        }
        __syncthreads();

        // ---- 2 k-atoms of m16n8k8
#pragma unroll
        for (int kk = 0; kk < 2; kk++) {
            const int kb = kk * 8 + lc;
            uint32_t a[2][4];
#pragma unroll
            for (int i = 0; i < 2; i++) {
                int r = warpM * 32 + i * 16 + gid;
                a[i][0] = __float_as_uint(As[kb][r]);
                a[i][1] = __float_as_uint(As[kb][r + 8]);
                a[i][2] = __float_as_uint(As[kb + 4][r]);
                a[i][3] = __float_as_uint(As[kb + 4][r + 8]);
            }
#pragma unroll
            for (int j = 0; j < 8; j++) {
                int cc = warpN * 64 + j * 8 + gid;
                uint32_t b0 = __float_as_uint(Bs[kb][cc]);
                uint32_t b1 = __float_as_uint(Bs[kb + 4][cc]);
                mma_tf32(acc[0][j], a[0], b0, b1);
                mma_tf32(acc[1][j], a[1], b0, b1);
            }
        }
        __syncthreads();
    }

    // ---- epilogue
#pragma unroll
    for (int i = 0; i < 2; i++) {
#pragma unroll
        for (int j = 0; j < 8; j++) {
            int col = warpN * 64 + j * 8 + 2 * lc;
            int row0 = blockM + warpM * 32 + i * 16 + gid;
            int row1 = row0 + 8;
            float v0 = acc[i][j][0], v1 = acc[i][j][1];
            float v2 = acc[i][j][2], v3 = acc[i][j][3];
            if (do_act) {
                float bb0 = bias[col], bb1 = bias[col + 1];
                v0 += bb0; v1 += bb1; v2 += bb0; v3 += bb1;
                v0 = (v0 > 0.f) ? v0 : expm1f(v0);
                v1 = (v1 > 0.f) ? v1 : expm1f(v1);
                v2 = (v2 > 0.f) ? v2 : expm1f(v2);
                v3 = (v3 > 0.f) ? v3 : expm1f(v3);
            }
            if (row0 < M)
                *(float2*)(C + (size_t)row0 * HID + col) = make_float2(v0, v1);
            if (row1 < M)
                *(float2*)(C + (size_t)row1 * HID + col) = make_float2(v2, v3);
        }
    }
}

// ---------------- scatter on raw x (64-wide): g_aggx[dst] += norm * x[src] --
__global__ void scatter_x_kernel(const float* __restrict__ x) {
    long long tid = (long long)blockIdx.x * blockDim.x + threadIdx.x;
    int e = (int)(tid >> 4);
    if (e >= N_EDGES) return;
    int c = (int)(tid & 15) << 2;
    int s = g_ei[e];
    int d = g_ei[N_EDGES + e];
    float nrm = g_norm[e];
    float4 v = *(const float4*)(x + (size_t)s * IN_CH + c);
    float* p = g_aggx + (size_t)d * IN_CH + c;
    asm volatile("red.global.add.v4.f32 [%0], {%1,%2,%3,%4};"
                 :: "l"(p), "f"(v.x * nrm), "f"(v.y * nrm),
                    "f"(v.z * nrm), "f"(v.w * nrm)
                 : "memory");
}

// ---------------- scatter on h (256-wide): g_agg[dst] += norm * g_h[src] ----
__global__ void scatter_kernel() {
    long long tid = (long long)blockIdx.x * blockDim.x + threadIdx.x;
    int e = (int)(tid >> 6);
    if (e >= N_EDGES) return;
    int c = (int)(tid & 63) << 2;
    int s = g_ei[e];
    int d = g_ei[N_EDGES + e];
    float nrm = g_norm[e];
    float4 v = *(const float4*)(g_h + (size_t)s * HID + c);
    float* p = g_agg + (size_t)d * HID + c;
    asm volatile("red.global.add.v4.f32 [%0], {%1,%2,%3,%4};"
                 :: "l"(p), "f"(v.x * nrm), "f"(v.y * nrm),
                    "f"(v.z * nrm), "f"(v.w * nrm)
                 : "memory");
}

// ---------------- epilogue: out = elu(agg + b) ------------------------------
__global__ void epilogue_kernel(const float* __restrict__ b,
                                float* __restrict__ extout, int use_ext) {
    int i = blockIdx.x * blockDim.x + threadIdx.x;   // over N*64 float4
    if (i >= N_NODES * (HID / 4)) return;
    int c = (i & 63) << 2;
    float4 v = ((const float4*)g_agg)[i];
    float4 bb = *(const float4*)(b + c);
    v.x += bb.x; v.y += bb.y; v.z += bb.z; v.w += bb.w;
    v.x = (v.x > 0.f) ? v.x : expm1f(v.x);
    v.y = (v.y > 0.f) ? v.y : expm1f(v.y);
    v.z = (v.z > 0.f) ? v.z : expm1f(v.z);
    v.w = (v.w > 0.f) ? v.w : expm1f(v.w);
    float* out = use_ext ? extout : g_x;
    ((float4*)out)[i] = v;
}

// ---------------- launch -----------------------------------------------------
extern "C" void kernel_launch(void* const* d_in, const int* in_sizes, int n_in,
                              void* d_out, int out_size) {
    const float* x  = (const float*)d_in[0];
    const void*  ei = d_in[1];
    const float* W1 = (const float*)d_in[2];
    const float* b1 = (const float*)d_in[3];
    const float* W2 = (const float*)d_in[4];
    const float* b2 = (const float*)d_in[5];
    const float* W3 = (const float*)d_in[6];
    const float* b3 = (const float*)d_in[7];
    float* out = (float*)d_out;

    const int TPB = 256;
    const int nodeBlocks = (N_NODES + TPB - 1) / TPB;
    const int edgeBlocks = (N_EDGES + TPB - 1) / TPB;
    const int ei2Blocks  = (2 * N_EDGES + TPB - 1) / TPB;
    const int featBlocks = (N_NODES * (HID / 4) + TPB - 1) / TPB;
    const int aggxBlocks = (N_NODES * (IN_CH / 4) + TPB - 1) / TPB;
    const int scatterBlocks  = (int)(((long long)N_EDGES * 64 + TPB - 1) / TPB);
    const int scatterXBlocks = (int)(((long long)N_EDGES * 16 + TPB - 1) / TPB);
    const int gemmBlocks = (N_NODES + 63) / 64;

    // edge prep + normalization
    probe_kernel<<<1, 256>>>((const unsigned int*)ei);
    convert_edges_kernel<<<ei2Blocks, TPB>>>(ei);
    zero_deg_kernel<<<nodeBlocks, TPB>>>();
    deg_count_kernel<<<edgeBlocks, TPB>>>();
    dinv_kernel<<<nodeBlocks, TPB>>>();
    norm_kernel<<<edgeBlocks, TPB>>>();

    // layer 1 (aggregate-first): aggx = A_norm x ; x' = elu(aggx @ W1 + b1)
    zero_aggx_kernel<<<aggxBlocks, TPB>>>();
    scatter_x_kernel<<<scatterXBlocks, TPB>>>(x);
    mma_gemm_kernel<<<gemmBlocks, 256>>>(nullptr, 1, W1, b1, nullptr, 2, IN_CH, 1);

    // layer 2: h = x' @ W2 ; agg = scatter(h) ; x'' = elu(agg + b2)
    mma_gemm_kernel<<<gemmBlocks, 256>>>(nullptr, 2, W2, nullptr, nullptr, 1, HID, 0);
    zero_agg_kernel<<<featBlocks, TPB>>>();
    scatter_kernel<<<scatterBlocks, TPB>>>();
    epilogue_kernel<<<featBlocks, TPB>>>(b2, nullptr, 0);

    // layer 3: h = x'' @ W3 ; agg = scatter(h) ; out = elu(agg + b3)
    mma_gemm_kernel<<<gemmBlocks, 256>>>(nullptr, 2, W3, nullptr, nullptr, 1, HID, 0);
    zero_agg_kernel<<<featBlocks, TPB>>>();
    scatter_kernel<<<scatterBlocks, TPB>>>();
    epilogue_kernel<<<featBlocks, TPB>>>(b3, out, 1);
}

// round 3
// speedup vs baseline: 2.6391x; 1.5473x over previous
#include <cuda_runtime.h>
#include <math.h>
#include <stdint.h>

#define N_NODES 100000
#define N_EDGES 600000
#define HID 256
#define IN_CH 64
#define SCAN_BLOCKS ((N_NODES + 1023) / 1024)   // 98

// ---------------- scratch (device globals; no allocation allowed) ----------
__device__ float g_h   [(size_t)N_NODES * HID];   // post-GEMM features
__device__ float g_x   [(size_t)N_NODES * HID];   // layer activations
__device__ float g_aggx[(size_t)N_NODES * IN_CH]; // layer-1 aggregated input
__device__ float g_dinv[N_NODES];
__device__ int   g_idg [N_NODES];                 // int in-degree
__device__ int   g_rowptr[N_NODES + 1];
__device__ int   g_cursor[N_NODES];
__device__ int   g_bsum[SCAN_BLOCKS];
__device__ int   g_boff[SCAN_BLOCKS];
__device__ int   g_csr_src[N_EDGES];
__device__ float g_csr_nrm[N_EDGES];
__device__ int   g_ei  [2 * N_EDGES];             // [0,E)=src, [E,2E)=dst
__device__ int   g_is64;

// ---------------- dtype probe: int64 vs int32 edge_index -------------------
__global__ void probe_kernel(const unsigned int* __restrict__ words) {
    __shared__ int nz;
    if (threadIdx.x == 0) nz = 0;
    __syncthreads();
    int local = 0;
    for (int i = threadIdx.x; i < 1024; i += blockDim.x)
        if (words[2 * i + 1] != 0u) local = 1;
    if (local) atomicOr(&nz, 1);
    __syncthreads();
    if (threadIdx.x == 0) g_is64 = (nz == 0) ? 1 : 0;
}

__global__ void convert_edges_kernel(const void* __restrict__ ei) {
    int i = blockIdx.x * blockDim.x + threadIdx.x;
    if (i >= 2 * N_EDGES) return;
    if (g_is64)
        g_ei[i] = (int)((const long long*)ei)[i];
    else
        g_ei[i] = ((const int*)ei)[i];
}

// ---------------- degree / dinv --------------------------------------------
__global__ void zero_idg_kernel() {
    int i = blockIdx.x * blockDim.x + threadIdx.x;
    if (i < N_NODES) g_idg[i] = 0;
}

__global__ void deg_count_kernel() {
    int e = blockIdx.x * blockDim.x + threadIdx.x;
    if (e < N_EDGES) atomicAdd(&g_idg[g_ei[N_EDGES + e]], 1);
}

__global__ void dinv_kernel() {
    int i = blockIdx.x * blockDim.x + threadIdx.x;
    if (i < N_NODES) {
        int d = g_idg[i];
        g_dinv[i] = (d > 0) ? rsqrtf((float)d) : 0.0f;
    }
}

// ---------------- CSR build: 3-phase exclusive scan + cursor fill ----------
__global__ __launch_bounds__(1024) void scan1_kernel() {
    __shared__ int sh[1024];
    int i = blockIdx.x * 1024 + threadIdx.x;
    int v = (i < N_NODES) ? g_idg[i] : 0;
    sh[threadIdx.x] = v;
    __syncthreads();
#pragma unroll
    for (int off = 1; off < 1024; off <<= 1) {
        int t = (threadIdx.x >= off) ? sh[threadIdx.x - off] : 0;
        __syncthreads();
        sh[threadIdx.x] += t;
        __syncthreads();
    }
    if (i < N_NODES) g_rowptr[i] = sh[threadIdx.x] - v;   // block-local exclusive
    if (threadIdx.x == 1023) g_bsum[blockIdx.x] = sh[1023];
}

__global__ void scan2_kernel() {
    __shared__ int sh[SCAN_BLOCKS];
    int tid = threadIdx.x;
    if (tid < SCAN_BLOCKS) sh[tid] = g_bsum[tid];
    __syncthreads();
    if (tid == 0) {
        int acc = 0;
        for (int b = 0; b < SCAN_BLOCKS; b++) { int t = sh[b]; sh[b] = acc; acc += t; }
    }
    __syncthreads();
    if (tid < SCAN_BLOCKS) g_boff[tid] = sh[tid];
}

__global__ void scan3_kernel() {
    int i = blockIdx.x * blockDim.x + threadIdx.x;
    if (i < N_NODES) {
        int r = g_rowptr[i] + g_boff[i >> 10];
        g_rowptr[i] = r;
        g_cursor[i] = r;
    }
    if (i == 0) g_rowptr[N_NODES] = N_EDGES;
}

__global__ void csr_fill_kernel() {
    int e = blockIdx.x * blockDim.x + threadIdx.x;
    if (e >= N_EDGES) return;
    int s = g_ei[e];
    int d = g_ei[N_EDGES + e];
    int pos = atomicAdd(&g_cursor[d], 1);
    g_csr_src[pos] = s;
    g_csr_nrm[pos] = g_dinv[s] * g_dinv[d];
}

// ---------------- tf32 helpers ----------------------------------------------
__device__ __forceinline__ float to_tf32(float x) {
    uint32_t u;
    asm("cvt.rna.tf32.f32 %0, %1;" : "=r"(u) : "f"(x));
    return __uint_as_float(u);
}

__device__ __forceinline__ void mma_tf32(float c[4], const uint32_t a[4],
                                         uint32_t b0, uint32_t b1) {
    asm volatile(
        "mma.sync.aligned.m16n8k8.row.col.f32.tf32.tf32.f32 "
        "{%0,%1,%2,%3}, {%4,%5,%6,%7}, {%8,%9}, {%0,%1,%2,%3};"
        : "+f"(c[0]), "+f"(c[1]), "+f"(c[2]), "+f"(c[3])
        : "r"(a[0]), "r"(a[1]), "r"(a[2]), "r"(a[3]), "r"(b0), "r"(b1));
}

// ---------------- tf32 tensor GEMM: C[M,256] = A[M,K] @ W[K,256] ------------
// BM=64, BN=256, BK=16, 8 warps (2m x 4n), warp tile 32x64.
// asel: 1 = g_aggx, 2 = g_x.  csel: 1 = g_h, 2 = g_x.  do_act: elu(acc+bias).
__global__ __launch_bounds__(256) void mma_gemm_kernel(
        int asel, const float* __restrict__ W, const float* __restrict__ bias,
        int csel, int K, int do_act) {
    const float* __restrict__ A = (asel == 1) ? g_aggx : g_x;
    float* __restrict__ C = (csel == 1) ? g_h : g_x;
    const int M = N_NODES;

    __shared__ __align__(16) float As[16][72];
    __shared__ __align__(16) float Bs[16][264];

    const int tid  = threadIdx.x;
    const int lane = tid & 31;
    const int warp = tid >> 5;
    const int warpM = warp & 1;
    const int warpN = warp >> 1;
    const int gid = lane >> 2;
    const int lc  = lane & 3;

    const int blockM = blockIdx.x * 64;

    const int am = tid >> 2;
    const int ak = (tid & 3) * 4;
    const int brow0 = tid >> 6;
    const int bcol  = (tid & 63) * 4;

    float acc[2][8][4];
#pragma unroll
    for (int i = 0; i < 2; i++)
#pragma unroll
        for (int j = 0; j < 8; j++)
#pragma unroll
            for (int v = 0; v < 4; v++) acc[i][j][v] = 0.0f;

    for (int k0 = 0; k0 < K; k0 += 16) {
        float4 av = make_float4(0.f, 0.f, 0.f, 0.f);
        int grow = blockM + am;
        if (grow < M)
            av = *(const float4*)(A + (size_t)grow * K + k0 + ak);
        As[ak + 0][am] = to_tf32(av.x);
        As[ak + 1][am] = to_tf32(av.y);
        As[ak + 2][am] = to_tf32(av.z);
        As[ak + 3][am] = to_tf32(av.w);

#pragma unroll
        for (int i = 0; i < 4; i++) {
            int row = brow0 + i * 4;
            float4 wv = *(const float4*)(W + (size_t)(k0 + row) * HID + bcol);
            float4 tv;
            tv.x = to_tf32(wv.x); tv.y = to_tf32(wv.y);
            tv.z = to_tf32(wv.z); tv.w = to_tf32(wv.w);
            *(float4*)&Bs[row][bcol] = tv;
        }
        __syncthreads();

#pragma unroll
        for (int kk = 0; kk < 2; kk++) {
            const int kb = kk * 8 + lc;
            uint32_t a[2][4];
#pragma unroll
            for (int i = 0; i < 2; i++) {
                int r = warpM * 32 + i * 16 + gid;
                a[i][0] = __float_as_uint(As[kb][r]);
                a[i][1] = __float_as_uint(As[kb][r + 8]);
                a[i][2] = __float_as_uint(As[kb + 4][r]);
                a[i][3] = __float_as_uint(As[kb + 4][r + 8]);
            }
#pragma unroll
            for (int j = 0; j < 8; j++) {
                int cc = warpN * 64 + j * 8 + gid;
                uint32_t b0 = __float_as_uint(Bs[kb][cc]);
                uint32_t b1 = __float_as_uint(Bs[kb + 4][cc]);
                mma_tf32(acc[0][j], a[0], b0, b1);
                mma_tf32(acc[1][j], a[1], b0, b1);
            }
        }
        __syncthreads();
    }

#pragma unroll
    for (int i = 0; i < 2; i++) {
#pragma unroll
        for (int j = 0; j < 8; j++) {
            int col = warpN * 64 + j * 8 + 2 * lc;
            int row0 = blockM + warpM * 32 + i * 16 + gid;
            int row1 = row0 + 8;
            float v0 = acc[i][j][0], v1 = acc[i][j][1];
            float v2 = acc[i][j][2], v3 = acc[i][j][3];
            if (do_act) {
                float bb0 = bias[col], bb1 = bias[col + 1];
                v0 += bb0; v1 += bb1; v2 += bb0; v3 += bb1;
                v0 = (v0 > 0.f) ? v0 : expm1f(v0);
                v1 = (v1 > 0.f) ? v1 : expm1f(v1);
                v2 = (v2 > 0.f) ? v2 : expm1f(v2);
                v3 = (v3 > 0.f) ? v3 : expm1f(v3);
            }
            if (row0 < M)
                *(float2*)(C + (size_t)row0 * HID + col) = make_float2(v0, v1);
            if (row1 < M)
                *(float2*)(C + (size_t)row1 * HID + col) = make_float2(v2, v3);
        }
    }
}

// ------- CSR gather (256-wide): out[n] = elu(sum_e nrm*h[src] + bias) -------
// One warp per destination node; 2 float4 per lane held in registers.
__global__ __launch_bounds__(256) void gather_h_kernel(
        const float* __restrict__ bias, float* __restrict__ extout, int outsel) {
    int w = (blockIdx.x * blockDim.x + threadIdx.x) >> 5;
    if (w >= N_NODES) return;
    int lane = threadIdx.x & 31;
    float* __restrict__ out = outsel ? g_x : extout;

    int beg = g_rowptr[w];
    int end = g_rowptr[w + 1];
    float4 a0 = make_float4(0.f, 0.f, 0.f, 0.f);
    float4 a1 = make_float4(0.f, 0.f, 0.f, 0.f);
    for (int e = beg; e < end; e++) {
        int s = g_csr_src[e];
        float nrm = g_csr_nrm[e];
        const float4* row = (const float4*)(g_h + (size_t)s * HID);
        float4 v0 = row[lane];
        float4 v1 = row[lane + 32];
        a0.x = fmaf(nrm, v0.x, a0.x); a0.y = fmaf(nrm, v0.y, a0.y);
        a0.z = fmaf(nrm, v0.z, a0.z); a0.w = fmaf(nrm, v0.w, a0.w);
        a1.x = fmaf(nrm, v1.x, a1.x); a1.y = fmaf(nrm, v1.y, a1.y);
        a1.z = fmaf(nrm, v1.z, a1.z); a1.w = fmaf(nrm, v1.w, a1.w);
    }
    float4 b0 = *(const float4*)(bias + 4 * lane);
    float4 b1 = *(const float4*)(bias + 128 + 4 * lane);
    a0.x += b0.x; a0.y += b0.y; a0.z += b0.z; a0.w += b0.w;
    a1.x += b1.x; a1.y += b1.y; a1.z += b1.z; a1.w += b1.w;
    a0.x = (a0.x > 0.f) ? a0.x : expm1f(a0.x);
    a0.y = (a0.y > 0.f) ? a0.y : expm1f(a0.y);
    a0.z = (a0.z > 0.f) ? a0.z : expm1f(a0.z);
    a0.w = (a0.w > 0.f) ? a0.w : expm1f(a0.w);
    a1.x = (a1.x > 0.f) ? a1.x : expm1f(a1.x);
    a1.y = (a1.y > 0.f) ? a1.y : expm1f(a1.y);
    a1.z = (a1.z > 0.f) ? a1.z : expm1f(a1.z);
    a1.w = (a1.w > 0.f) ? a1.w : expm1f(a1.w);
    float4* orow = (float4*)(out + (size_t)w * HID);
    orow[lane] = a0;
    orow[lane + 32] = a1;
}

// ------- CSR gather (64-wide, layer 1): g_aggx[n] = sum_e nrm * x[src] ------
__global__ __launch_bounds__(256) void gather_x_kernel(const float* __restrict__ x) {
    int w = (blockIdx.x * blockDim.x + threadIdx.x) >> 5;
    if (w >= N_NODES) return;
    int lane = threadIdx.x & 31;

    int beg = g_rowptr[w];
    int end = g_rowptr[w + 1];
    float2 a = make_float2(0.f, 0.f);
    for (int e = beg; e < end; e++) {
        int s = g_csr_src[e];
        float nrm = g_csr_nrm[e];
        float2 v = ((const float2*)(x + (size_t)s * IN_CH))[lane];
        a.x = fmaf(nrm, v.x, a.x);
        a.y = fmaf(nrm, v.y, a.y);
    }
    ((float2*)(g_aggx + (size_t)w * IN_CH))[lane] = a;
}

// ---------------- launch -----------------------------------------------------
extern "C" void kernel_launch(void* const* d_in, const int* in_sizes, int n_in,
                              void* d_out, int out_size) {
    const float* x  = (const float*)d_in[0];
    const void*  ei = d_in[1];
    const float* W1 = (const float*)d_in[2];
    const float* b1 = (const float*)d_in[3];
    const float* W2 = (const float*)d_in[4];
    const float* b2 = (const float*)d_in[5];
    const float* W3 = (const float*)d_in[6];
    const float* b3 = (const float*)d_in[7];
    float* out = (float*)d_out;

    const int TPB = 256;
    const int nodeBlocks = (N_NODES + TPB - 1) / TPB;
    const int edgeBlocks = (N_EDGES + TPB - 1) / TPB;
    const int ei2Blocks  = (2 * N_EDGES + TPB - 1) / TPB;
    const int warpNodeBlocks = (N_NODES * 32 + TPB - 1) / TPB;  // 1 warp/node
    const int gemmBlocks = (N_NODES + 63) / 64;

    // ---- prep: edges, degree, CSR
    probe_kernel<<<1, 256>>>((const unsigned int*)ei);
    convert_edges_kernel<<<ei2Blocks, TPB>>>(ei);
    zero_idg_kernel<<<nodeBlocks, TPB>>>();
    deg_count_kernel<<<edgeBlocks, TPB>>>();
    dinv_kernel<<<nodeBlocks, TPB>>>();
    scan1_kernel<<<SCAN_BLOCKS, 1024>>>();
    scan2_kernel<<<1, 128>>>();
    scan3_kernel<<<nodeBlocks, TPB>>>();
    csr_fill_kernel<<<edgeBlocks, TPB>>>();

    // ---- layer 1 (aggregate-first): aggx = A_norm x ; x' = elu(aggx W1 + b1)
    gather_x_kernel<<<warpNodeBlocks, TPB>>>(x);
    mma_gemm_kernel<<<gemmBlocks, 256>>>(1, W1, b1, 2, IN_CH, 1);

    // ---- layer 2: h = x' W2 ; x'' = elu(A_norm h + b2)
    mma_gemm_kernel<<<gemmBlocks, 256>>>(2, W2, nullptr, 1, HID, 0);
    gather_h_kernel<<<warpNodeBlocks, TPB>>>(b2, nullptr, 1);

    // ---- layer 3: h = x'' W3 ; out = elu(A_norm h + b3)
    mma_gemm_kernel<<<gemmBlocks, 256>>>(2, W3, nullptr, 1, HID, 0);
    gather_h_kernel<<<warpNodeBlocks, TPB>>>(b3, out, 0);
}

// round 4
// speedup vs baseline: 3.1231x; 1.1834x over previous
#include <cuda_runtime.h>
#include <math.h>
#include <stdint.h>

#define N_NODES 100000
#define N_EDGES 600000
#define HID 256
#define IN_CH 64
#define SCAN_BLOCKS ((N_NODES + 1023) / 1024)   // 98

// ---------------- scratch (device globals; no allocation allowed) ----------
__device__ float g_h   [(size_t)N_NODES * HID];   // post-GEMM features
__device__ float g_x   [(size_t)N_NODES * HID];   // layer activations
__device__ float g_aggx[(size_t)N_NODES * IN_CH]; // layer-1 aggregated input
__device__ float g_wt  [HID * HID];               // pre-rounded tf32 weights
__device__ float g_dinv[N_NODES];
__device__ int   g_idg [N_NODES];                 // int in-degree
__device__ int   g_rowptr[N_NODES + 1];
__device__ int   g_cursor[N_NODES];
__device__ int   g_bsum[SCAN_BLOCKS];
__device__ int   g_boff[SCAN_BLOCKS];
__device__ int   g_csr_src[N_EDGES];
__device__ float g_csr_nrm[N_EDGES];
__device__ int   g_ei  [2 * N_EDGES];             // [0,E)=src, [E,2E)=dst
__device__ int   g_is64;

// ---------------- dtype probe: int64 vs int32 edge_index -------------------
__global__ void probe_kernel(const unsigned int* __restrict__ words) {
    __shared__ int nz;
    if (threadIdx.x == 0) nz = 0;
    __syncthreads();
    int local = 0;
    for (int i = threadIdx.x; i < 1024; i += blockDim.x)
        if (words[2 * i + 1] != 0u) local = 1;
    if (local) atomicOr(&nz, 1);
    __syncthreads();
    if (threadIdx.x == 0) g_is64 = (nz == 0) ? 1 : 0;
}

__global__ void convert_edges_kernel(const void* __restrict__ ei) {
    int i = blockIdx.x * blockDim.x + threadIdx.x;
    if (i >= 2 * N_EDGES) return;
    if (g_is64)
        g_ei[i] = (int)((const long long*)ei)[i];
    else
        g_ei[i] = ((const int*)ei)[i];
}

// ---------------- degree / dinv --------------------------------------------
__global__ void zero_idg_kernel() {
    int i = blockIdx.x * blockDim.x + threadIdx.x;
    if (i < N_NODES) g_idg[i] = 0;
}

__global__ void deg_count_kernel() {
    int e = blockIdx.x * blockDim.x + threadIdx.x;
    if (e < N_EDGES) atomicAdd(&g_idg[g_ei[N_EDGES + e]], 1);
}

__global__ void dinv_kernel() {
    int i = blockIdx.x * blockDim.x + threadIdx.x;
    if (i < N_NODES) {
        int d = g_idg[i];
        g_dinv[i] = (d > 0) ? rsqrtf((float)d) : 0.0f;
    }
}

// ---------------- CSR build: 3-phase exclusive scan + cursor fill ----------
__global__ __launch_bounds__(1024) void scan1_kernel() {
    __shared__ int sh[1024];
    int i = blockIdx.x * 1024 + threadIdx.x;
    int v = (i < N_NODES) ? g_idg[i] : 0;
    sh[threadIdx.x] = v;
    __syncthreads();
#pragma unroll
    for (int off = 1; off < 1024; off <<= 1) {
        int t = (threadIdx.x >= off) ? sh[threadIdx.x - off] : 0;
        __syncthreads();
        sh[threadIdx.x] += t;
        __syncthreads();
    }
    if (i < N_NODES) g_rowptr[i] = sh[threadIdx.x] - v;   // block-local exclusive
    if (threadIdx.x == 1023) g_bsum[blockIdx.x] = sh[1023];
}

__global__ void scan2_kernel() {
    __shared__ int sh[SCAN_BLOCKS];
    int tid = threadIdx.x;
    if (tid < SCAN_BLOCKS) sh[tid] = g_bsum[tid];
    __syncthreads();
    if (tid == 0) {
        int acc = 0;
        for (int b = 0; b < SCAN_BLOCKS; b++) { int t = sh[b]; sh[b] = acc; acc += t; }
    }
    __syncthreads();
    if (tid < SCAN_BLOCKS) g_boff[tid] = sh[tid];
}

__global__ void scan3_kernel() {
    int i = blockIdx.x * blockDim.x + threadIdx.x;
    if (i < N_NODES) {
        int r = g_rowptr[i] + g_boff[i >> 10];
        g_rowptr[i] = r;
        g_cursor[i] = r;
    }
    if (i == 0) g_rowptr[N_NODES] = N_EDGES;
}

__global__ void csr_fill_kernel() {
    int e = blockIdx.x * blockDim.x + threadIdx.x;
    if (e >= N_EDGES) return;
    int s = g_ei[e];
    int d = g_ei[N_EDGES + e];
    int pos = atomicAdd(&g_cursor[d], 1);
    g_csr_src[pos] = s;
    g_csr_nrm[pos] = g_dinv[s] * g_dinv[d];
}

// ---------------- tf32 helpers ----------------------------------------------
__device__ __forceinline__ float to_tf32(float x) {
    uint32_t u;
    asm("cvt.rna.tf32.f32 %0, %1;" : "=r"(u) : "f"(x));
    return __uint_as_float(u);
}

__device__ __forceinline__ void mma_tf32(float c[4], const uint32_t a[4],
                                         uint32_t b0, uint32_t b1) {
    asm volatile(
        "mma.sync.aligned.m16n8k8.row.col.f32.tf32.tf32.f32 "
        "{%0,%1,%2,%3}, {%4,%5,%6,%7}, {%8,%9}, {%0,%1,%2,%3};"
        : "+f"(c[0]), "+f"(c[1]), "+f"(c[2]), "+f"(c[3])
        : "r"(a[0]), "r"(a[1]), "r"(a[2]), "r"(a[3]), "r"(b0), "r"(b1));
}

__device__ __forceinline__ void cp16(float* dst, const float* src, int srcsz) {
    uint32_t d = (uint32_t)__cvta_generic_to_shared(dst);
    asm volatile("cp.async.ca.shared.global [%0], [%1], 16, %2;"
                 :: "r"(d), "l"(src), "r"(srcsz));
}

// ---------------- weight pre-round -----------------------------------------
__global__ void round_w_kernel(const float* __restrict__ W, int n) {
    int i = blockIdx.x * blockDim.x + threadIdx.x;
    if (i < n) g_wt[i] = to_tf32(W[i]);
}

// ---------------- pipelined tf32 GEMM: C[M,256] = A[M,K] @ g_wt[K,256] ------
// BM=64, BN=256, BK=16, double-buffered cp.async, 8 warps (2m x 4n),
// warp tile 32x64.  A inputs are pre-rounded tf32 (producers round at write).
// asel: 1 = g_aggx, 2 = g_x.  csel: 1 = g_h, 2 = g_x (rounded for next GEMM).
#define ASTRIDE 20
#define BSTRIDE 264
__global__ __launch_bounds__(256) void mma_gemm_kernel(
        int asel, const float* __restrict__ bias, int csel, int K, int do_act) {
    const float* __restrict__ A = (asel == 1) ? g_aggx : g_x;
    float* __restrict__ C = (csel == 1) ? g_h : g_x;
    const int M = N_NODES;

    __shared__ __align__(16) float As[2][64][ASTRIDE];
    __shared__ __align__(16) float Bs[2][16][BSTRIDE];

    const int tid  = threadIdx.x;
    const int lane = tid & 31;
    const int warp = tid >> 5;
    const int warpM = warp & 1;
    const int warpN = warp >> 1;
    const int gid = lane >> 2;
    const int lc  = lane & 3;
    const int blockM = blockIdx.x * 64;

    // load maps
    const int arow = tid >> 2;          // 0..63
    const int akq  = (tid & 3) * 4;     // 0,4,8,12
    const int brow = tid >> 6;          // 0..3 (+4*i)
    const int bnq  = (tid & 63) * 4;    // 0..252

    const int agrow = blockM + arow;
    const float* asrc = A + (size_t)agrow * K + akq;
    const int apred = (agrow < M) ? 16 : 0;

    float acc[2][8][4];
#pragma unroll
    for (int i = 0; i < 2; i++)
#pragma unroll
        for (int j = 0; j < 8; j++)
#pragma unroll
            for (int v = 0; v < 4; v++) acc[i][j][v] = 0.0f;

    const int nk = K / 16;

    // prologue: stage 0
    cp16(&As[0][arow][akq], asrc, apred);
#pragma unroll
    for (int i = 0; i < 4; i++) {
        int r = brow + i * 4;
        cp16(&Bs[0][r][bnq], g_wt + (size_t)r * HID + bnq, 16);
    }
    asm volatile("cp.async.commit_group;");

    for (int it = 0; it < nk; it++) {
        if (it + 1 < nk) {
            int k0 = (it + 1) * 16;
            int nb = (it + 1) & 1;
            cp16(&As[nb][arow][akq], asrc + k0, apred);
#pragma unroll
            for (int i = 0; i < 4; i++) {
                int r = brow + i * 4;
                cp16(&Bs[nb][r][bnq], g_wt + (size_t)(k0 + r) * HID + bnq, 16);
            }
        }
        asm volatile("cp.async.commit_group;");
        asm volatile("cp.async.wait_group 1;");
        __syncthreads();

        const int b = it & 1;
#pragma unroll
        for (int kk = 0; kk < 2; kk++) {
            const int kb = kk * 8 + lc;
            uint32_t a[2][4];
#pragma unroll
            for (int i = 0; i < 2; i++) {
                int r = warpM * 32 + i * 16 + gid;
                a[i][0] = __float_as_uint(As[b][r][kb]);
                a[i][1] = __float_as_uint(As[b][r + 8][kb]);
                a[i][2] = __float_as_uint(As[b][r][kb + 4]);
                a[i][3] = __float_as_uint(As[b][r + 8][kb + 4]);
            }
#pragma unroll
            for (int j = 0; j < 8; j++) {
                int cc = warpN * 64 + j * 8 + gid;
                uint32_t b0 = __float_as_uint(Bs[b][kb][cc]);
                uint32_t b1 = __float_as_uint(Bs[b][kb + 4][cc]);
                mma_tf32(acc[0][j], a[0], b0, b1);
                mma_tf32(acc[1][j], a[1], b0, b1);
            }
        }
        __syncthreads();
    }

    // ---- epilogue
#pragma unroll
    for (int i = 0; i < 2; i++) {
#pragma unroll
        for (int j = 0; j < 8; j++) {
            int col = warpN * 64 + j * 8 + 2 * lc;
            int row0 = blockM + warpM * 32 + i * 16 + gid;
            int row1 = row0 + 8;
            float v0 = acc[i][j][0], v1 = acc[i][j][1];
            float v2 = acc[i][j][2], v3 = acc[i][j][3];
            if (do_act) {
                float bb0 = bias[col], bb1 = bias[col + 1];
                v0 += bb0; v1 += bb1; v2 += bb0; v3 += bb1;
                v0 = (v0 > 0.f) ? v0 : expm1f(v0);
                v1 = (v1 > 0.f) ? v1 : expm1f(v1);
                v2 = (v2 > 0.f) ? v2 : expm1f(v2);
                v3 = (v3 > 0.f) ? v3 : expm1f(v3);
            }
            if (csel == 2) {   // feeds next GEMM: pre-round to tf32
                v0 = to_tf32(v0); v1 = to_tf32(v1);
                v2 = to_tf32(v2); v3 = to_tf32(v3);
            }
            if (row0 < M)
                *(float2*)(C + (size_t)row0 * HID + col) = make_float2(v0, v1);
            if (row1 < M)
                *(float2*)(C + (size_t)row1 * HID + col) = make_float2(v2, v3);
        }
    }
}

// ------- CSR gather (256-wide): out[n] = elu(sum_e nrm*h[src] + bias) -------
// outsel 1: write g_x rounded to tf32 (feeds next GEMM); 0: write extout raw.
__global__ __launch_bounds__(256) void gather_h_kernel(
        const float* __restrict__ bias, float* __restrict__ extout, int outsel) {
    int w = (blockIdx.x * blockDim.x + threadIdx.x) >> 5;
    if (w >= N_NODES) return;
    int lane = threadIdx.x & 31;
    float* __restrict__ out = outsel ? g_x : extout;

    int beg = g_rowptr[w];
    int end = g_rowptr[w + 1];
    float4 a0 = make_float4(0.f, 0.f, 0.f, 0.f);
    float4 a1 = make_float4(0.f, 0.f, 0.f, 0.f);
    for (int e = beg; e < end; e++) {
        int s = g_csr_src[e];
        float nrm = g_csr_nrm[e];
        const float4* row = (const float4*)(g_h + (size_t)s * HID);
        float4 v0 = row[lane];
        float4 v1 = row[lane + 32];
        a0.x = fmaf(nrm, v0.x, a0.x); a0.y = fmaf(nrm, v0.y, a0.y);
        a0.z = fmaf(nrm, v0.z, a0.z); a0.w = fmaf(nrm, v0.w, a0.w);
        a1.x = fmaf(nrm, v1.x, a1.x); a1.y = fmaf(nrm, v1.y, a1.y);
        a1.z = fmaf(nrm, v1.z, a1.z); a1.w = fmaf(nrm, v1.w, a1.w);
    }
    float4 b0 = *(const float4*)(bias + 4 * lane);
    float4 b1 = *(const float4*)(bias + 128 + 4 * lane);
    a0.x += b0.x; a0.y += b0.y; a0.z += b0.z; a0.w += b0.w;
    a1.x += b1.x; a1.y += b1.y; a1.z += b1.z; a1.w += b1.w;
    a0.x = (a0.x > 0.f) ? a0.x : expm1f(a0.x);
    a0.y = (a0.y > 0.f) ? a0.y : expm1f(a0.y);
    a0.z = (a0.z > 0.f) ? a0.z : expm1f(a0.z);
    a0.w = (a0.w > 0.f) ? a0.w : expm1f(a0.w);
    a1.x = (a1.x > 0.f) ? a1.x : expm1f(a1.x);
    a1.y = (a1.y > 0.f) ? a1.y : expm1f(a1.y);
    a1.z = (a1.z > 0.f) ? a1.z : expm1f(a1.z);
    a1.w = (a1.w > 0.f) ? a1.w : expm1f(a1.w);
    if (outsel) {
        a0.x = to_tf32(a0.x); a0.y = to_tf32(a0.y);
        a0.z = to_tf32(a0.z); a0.w = to_tf32(a0.w);
        a1.x = to_tf32(a1.x); a1.y = to_tf32(a1.y);
        a1.z = to_tf32(a1.z); a1.w = to_tf32(a1.w);
    }
    float4* orow = (float4*)(out + (size_t)w * HID);
    orow[lane] = a0;
    orow[lane + 32] = a1;
}

// ------- CSR gather (64-wide, layer 1): g_aggx[n] = sum_e nrm * x[src] ------
// Output rounded to tf32 (feeds GEMM1).
__global__ __launch_bounds__(256) void gather_x_kernel(const float* __restrict__ x) {
    int w = (blockIdx.x * blockDim.x + threadIdx.x) >> 5;
    if (w >= N_NODES) return;
    int lane = threadIdx.x & 31;

    int beg = g_rowptr[w];
    int end = g_rowptr[w + 1];
    float2 a = make_float2(0.f, 0.f);
    for (int e = beg; e < end; e++) {
        int s = g_csr_src[e];
        float nrm = g_csr_nrm[e];
        float2 v = ((const float2*)(x + (size_t)s * IN_CH))[lane];
        a.x = fmaf(nrm, v.x, a.x);
        a.y = fmaf(nrm, v.y, a.y);
    }
    a.x = to_tf32(a.x);
    a.y = to_tf32(a.y);
    ((float2*)(g_aggx + (size_t)w * IN_CH))[lane] = a;
}

// ---------------- launch -----------------------------------------------------
extern "C" void kernel_launch(void* const* d_in, const int* in_sizes, int n_in,
                              void* d_out, int out_size) {
    const float* x  = (const float*)d_in[0];
    const void*  ei = d_in[1];
    const float* W1 = (const float*)d_in[2];
    const float* b1 = (const float*)d_in[3];
    const float* W2 = (const float*)d_in[4];
    const float* b2 = (const float*)d_in[5];
    const float* W3 = (const float*)d_in[6];
    const float* b3 = (const float*)d_in[7];
    float* out = (float*)d_out;

    const int TPB = 256;
    const int nodeBlocks = (N_NODES + TPB - 1) / TPB;
    const int edgeBlocks = (N_EDGES + TPB - 1) / TPB;
    const int ei2Blocks  = (2 * N_EDGES + TPB - 1) / TPB;
    const int warpNodeBlocks = (N_NODES * 32 + TPB - 1) / TPB;  // 1 warp/node
    const int gemmBlocks = (N_NODES + 63) / 64;
    const int w1Blocks = (IN_CH * HID + TPB - 1) / TPB;
    const int w2Blocks = (HID * HID + TPB - 1) / TPB;

    // ---- prep: edges, degree, CSR
    probe_kernel<<<1, 256>>>((const unsigned int*)ei);
    convert_edges_kernel<<<ei2Blocks, TPB>>>(ei);
    zero_idg_kernel<<<nodeBlocks, TPB>>>();
    deg_count_kernel<<<edgeBlocks, TPB>>>();
    dinv_kernel<<<nodeBlocks, TPB>>>();
    scan1_kernel<<<SCAN_BLOCKS, 1024>>>();
    scan2_kernel<<<1, 128>>>();
    scan3_kernel<<<nodeBlocks, TPB>>>();
    csr_fill_kernel<<<edgeBlocks, TPB>>>();

    // ---- layer 1 (aggregate-first): aggx = A_norm x ; x' = elu(aggx W1 + b1)
    gather_x_kernel<<<warpNodeBlocks, TPB>>>(x);
    round_w_kernel<<<w1Blocks, TPB>>>(W1, IN_CH * HID);
    mma_gemm_kernel<<<gemmBlocks, 256>>>(1, b1, 2, IN_CH, 1);

    // ---- layer 2: h = x' W2 ; x'' = elu(A_norm h + b2)
    round_w_kernel<<<w2Blocks, TPB>>>(W2, HID * HID);
    mma_gemm_kernel<<<gemmBlocks, 256>>>(2, nullptr, 1, HID, 0);
    gather_h_kernel<<<warpNodeBlocks, TPB>>>(b2, nullptr, 1);

    // ---- layer 3: h = x'' W3 ; out = elu(A_norm h + b3)
    round_w_kernel<<<w2Blocks, TPB>>>(W3, HID * HID);
    mma_gemm_kernel<<<gemmBlocks, 256>>>(2, nullptr, 1, HID, 0);
    gather_h_kernel<<<warpNodeBlocks, TPB>>>(b3, out, 0);
}

// round 6
// speedup vs baseline: 4.3158x; 1.3819x over previous
#include <cuda_runtime.h>
#include <cuda_fp16.h>
#include <math.h>
#include <stdint.h>

#define N_NODES 100000
#define N_EDGES 600000
#define HID 256
#define IN_CH 64
#define SCAN_BLOCKS ((N_NODES + 1023) / 1024)   // 98

// ---------------- scratch (device globals; no allocation allowed) ----------
__device__ __half g_h   [(size_t)N_NODES * HID];   // post-GEMM features (fp16)
__device__ __half g_x   [(size_t)N_NODES * HID];   // layer activations (fp16)
__device__ __half g_aggx[(size_t)N_NODES * IN_CH]; // layer-1 aggregated input
__device__ __half g_wT  [HID * HID];               // W^T [N][K] fp16
__device__ float  g_dinv[N_NODES];
__device__ int    g_idg [N_NODES];
__device__ int    g_rowptr[N_NODES + 1];
__device__ int    g_cursor[N_NODES];
__device__ int    g_bsum[SCAN_BLOCKS];
__device__ int    g_boff[SCAN_BLOCKS];
__device__ int    g_csr_src[N_EDGES];
__device__ float  g_csr_nrm[N_EDGES];
__device__ int    g_ei  [2 * N_EDGES];
__device__ int    g_is64;

// ---------------- helpers ----------------------------------------------------
__device__ __forceinline__ void cp16(const void* dstp, const void* src, int srcsz) {
    uint32_t d = (uint32_t)__cvta_generic_to_shared(dstp);
    asm volatile("cp.async.ca.shared.global [%0], [%1], 16, %2;"
                 :: "r"(d), "l"(src), "r"(srcsz));
}

__device__ __forceinline__ void mma_f16(float c[4], const uint32_t a[4],
                                        uint32_t b0, uint32_t b1) {
    asm volatile(
        "mma.sync.aligned.m16n8k16.row.col.f32.f16.f16.f32 "
        "{%0,%1,%2,%3}, {%4,%5,%6,%7}, {%8,%9}, {%0,%1,%2,%3};"
        : "+f"(c[0]), "+f"(c[1]), "+f"(c[2]), "+f"(c[3])
        : "r"(a[0]), "r"(a[1]), "r"(a[2]), "r"(a[3]), "r"(b0), "r"(b1));
}

// ---------------- dtype probe / edge convert --------------------------------
__global__ void probe_kernel(const unsigned int* __restrict__ words) {
    __shared__ int nz;
    if (threadIdx.x == 0) nz = 0;
    __syncthreads();
    int local = 0;
    for (int i = threadIdx.x; i < 1024; i += blockDim.x)
        if (words[2 * i + 1] != 0u) local = 1;
    if (local) atomicOr(&nz, 1);
    __syncthreads();
    if (threadIdx.x == 0) g_is64 = (nz == 0) ? 1 : 0;
}

__global__ void convert_edges_kernel(const void* __restrict__ ei) {
    int i = blockIdx.x * blockDim.x + threadIdx.x;
    if (i >= 2 * N_EDGES) return;
    if (g_is64)
        g_ei[i] = (int)((const long long*)ei)[i];
    else
        g_ei[i] = ((const int*)ei)[i];
}

// ---------------- degree / dinv ---------------------------------------------
__global__ void zero_idg_kernel() {
    int i = blockIdx.x * blockDim.x + threadIdx.x;
    if (i < N_NODES) g_idg[i] = 0;
}

__global__ void deg_count_kernel() {
    int e = blockIdx.x * blockDim.x + threadIdx.x;
    if (e < N_EDGES) atomicAdd(&g_idg[g_ei[N_EDGES + e]], 1);
}

__global__ void dinv_kernel() {
    int i = blockIdx.x * blockDim.x + threadIdx.x;
    if (i < N_NODES) {
        int d = g_idg[i];
        g_dinv[i] = (d > 0) ? rsqrtf((float)d) : 0.0f;
    }
}

// ---------------- CSR build --------------------------------------------------
__global__ __launch_bounds__(1024) void scan1_kernel() {
    __shared__ int sh[1024];
    int i = blockIdx.x * 1024 + threadIdx.x;
    int v = (i < N_NODES) ? g_idg[i] : 0;
    sh[threadIdx.x] = v;
    __syncthreads();
#pragma unroll
    for (int off = 1; off < 1024; off <<= 1) {
        int t = (threadIdx.x >= off) ? sh[threadIdx.x - off] : 0;
        __syncthreads();
        sh[threadIdx.x] += t;
        __syncthreads();
    }
    if (i < N_NODES) g_rowptr[i] = sh[threadIdx.x] - v;
    if (threadIdx.x == 1023) g_bsum[blockIdx.x] = sh[1023];
}

__global__ void scan2_kernel() {
    __shared__ int sh[SCAN_BLOCKS];
    int tid = threadIdx.x;
    if (tid < SCAN_BLOCKS) sh[tid] = g_bsum[tid];
    __syncthreads();
    if (tid == 0) {
        int acc = 0;
        for (int b = 0; b < SCAN_BLOCKS; b++) { int t = sh[b]; sh[b] = acc; acc += t; }
    }
    __syncthreads();
    if (tid < SCAN_BLOCKS) g_boff[tid] = sh[tid];
}

__global__ void scan3_kernel() {
    int i = blockIdx.x * blockDim.x + threadIdx.x;
    if (i < N_NODES) {
        int r = g_rowptr[i] + g_boff[i >> 10];
        g_rowptr[i] = r;
        g_cursor[i] = r;
    }
    if (i == 0) g_rowptr[N_NODES] = N_EDGES;
}

__global__ void csr_fill_kernel() {
    int e = blockIdx.x * blockDim.x + threadIdx.x;
    if (e >= N_EDGES) return;
    int s = g_ei[e];
    int d = g_ei[N_EDGES + e];
    int pos = atomicAdd(&g_cursor[d], 1);
    g_csr_src[pos] = s;
    g_csr_nrm[pos] = g_dinv[s] * g_dinv[d];
}

// -------- weight transpose + fp16 convert: g_wT[n][k] = h(W[k][n]) ----------
__global__ void transT_w_kernel(const float* __restrict__ W, int K) {
    __shared__ float t[32][33];
    int kb = blockIdx.x * 32, nb = blockIdx.y * 32;
    int tx = threadIdx.x, ty = threadIdx.y;     // block 32x8
#pragma unroll
    for (int j = 0; j < 32; j += 8)
        t[ty + j][tx] = W[(size_t)(kb + ty + j) * HID + nb + tx];
    __syncthreads();
#pragma unroll
    for (int j = 0; j < 32; j += 8)
        g_wT[(size_t)(nb + ty + j) * K + kb + tx] = __float2half_rn(t[tx][ty + j]);
}

// ---------------- fp16 tensor GEMM: C[M,256] = A[M,K] @ W[K,256] -------------
// BM=128, BN=128 (gridDim.y=2), BK=32 halves, double-buffered cp.async.
// 8 warps: warpM=warp&3 (32-row groups), warpN=warp>>2 (64-col groups);
// warp tile 32x64: 2 m-atoms x 8 n-atoms of m16n8k16.
// asel: 1 = g_aggx (K=64), 2 = g_x.  csel: 1 = g_h, 2 = g_x.
#define HSTR 40   // halves per smem row (80B, 16B-aligned, conflict-free)
__global__ __launch_bounds__(256) void hgemm_kernel(
        int asel, const float* __restrict__ bias, int csel, int K, int do_act) {
    const __half* __restrict__ A = (asel == 1) ? g_aggx : g_x;
    __half* __restrict__ C = (csel == 1) ? g_h : g_x;
    const int M = N_NODES;

    __shared__ __align__(16) __half As[2][128][HSTR];
    __shared__ __align__(16) __half Bs[2][128][HSTR];

    const int tid  = threadIdx.x;
    const int lane = tid & 31;
    const int warp = tid >> 5;
    const int warpM = warp & 3;
    const int warpN = warp >> 2;
    const int gid = lane >> 2;
    const int lc  = lane & 3;
    const int blockM = blockIdx.x * 128;
    const int blockN = blockIdx.y * 128;

    float acc[2][8][4];
#pragma unroll
    for (int i = 0; i < 2; i++)
#pragma unroll
        for (int j = 0; j < 8; j++)
#pragma unroll
            for (int v = 0; v < 4; v++) acc[i][j][v] = 0.0f;

    const int nk = K / 32;

    // tile loader: 2 cp.async each for A and B per thread
    auto load_stage = [&](int buf, int k0) {
#pragma unroll
        for (int i = 0; i < 2; i++) {
            int idx = tid + i * 256;
            int r = idx >> 2, seg = (idx & 3) * 8;
            int grow = blockM + r;
            const __half* asrc = A + (size_t)((grow < M) ? grow : M - 1) * K + k0 + seg;
            cp16(&As[buf][r][seg], asrc, (grow < M) ? 16 : 0);
            const __half* bsrc = g_wT + (size_t)(blockN + r) * K + k0 + seg;
            cp16(&Bs[buf][r][seg], bsrc, 16);
        }
    };

    load_stage(0, 0);
    asm volatile("cp.async.commit_group;" ::: "memory");

    for (int it = 0; it < nk; it++) {
        if (it + 1 < nk)
            load_stage((it + 1) & 1, (it + 1) * 32);
        asm volatile("cp.async.commit_group;" ::: "memory");
        asm volatile("cp.async.wait_group 1;" ::: "memory");
        __syncthreads();

        const int b = it & 1;
#pragma unroll
        for (int kk = 0; kk < 2; kk++) {
            const int kb = kk * 16 + 2 * lc;
            uint32_t a[2][4];
#pragma unroll
            for (int i = 0; i < 2; i++) {
                int r = warpM * 32 + i * 16 + gid;
                a[i][0] = *(const uint32_t*)&As[b][r][kb];
                a[i][1] = *(const uint32_t*)&As[b][r + 8][kb];
                a[i][2] = *(const uint32_t*)&As[b][r][kb + 8];
                a[i][3] = *(const uint32_t*)&As[b][r + 8][kb + 8];
            }
#pragma unroll
            for (int j = 0; j < 8; j++) {
                int cc = warpN * 64 + j * 8 + gid;
                uint32_t b0 = *(const uint32_t*)&Bs[b][cc][kb];
                uint32_t b1 = *(const uint32_t*)&Bs[b][cc][kb + 8];
                mma_f16(acc[0][j], a[0], b0, b1);
                mma_f16(acc[1][j], a[1], b0, b1);
            }
        }
        __syncthreads();
    }

    // ---- epilogue: fp32 bias+ELU, round-to-fp16 store
#pragma unroll
    for (int i = 0; i < 2; i++) {
#pragma unroll
        for (int j = 0; j < 8; j++) {
            int col = blockN + warpN * 64 + j * 8 + 2 * lc;
            int row0 = blockM + warpM * 32 + i * 16 + gid;
            int row1 = row0 + 8;
            float v0 = acc[i][j][0], v1 = acc[i][j][1];
            float v2 = acc[i][j][2], v3 = acc[i][j][3];
            if (do_act) {
                float bb0 = bias[col], bb1 = bias[col + 1];
                v0 += bb0; v1 += bb1; v2 += bb0; v3 += bb1;
                v0 = (v0 > 0.f) ? v0 : expm1f(v0);
                v1 = (v1 > 0.f) ? v1 : expm1f(v1);
                v2 = (v2 > 0.f) ? v2 : expm1f(v2);
                v3 = (v3 > 0.f) ? v3 : expm1f(v3);
            }
            if (row0 < M)
                *(__half2*)(C + (size_t)row0 * HID + col) = __floats2half2_rn(v0, v1);
            if (row1 < M)
                *(__half2*)(C + (size_t)row1 * HID + col) = __floats2half2_rn(v2, v3);
        }
    }
}

// ------- CSR gather (256-wide fp16 rows): elu(sum nrm*h[src] + bias) --------
// One warp per node; each lane owns 8 consecutive cols (one uint4 of halves).
// outsel 1: write g_x (fp16). outsel 0: write extout (fp32, final output).
__global__ __launch_bounds__(256) void gather_h_kernel(
        const float* __restrict__ bias, float* __restrict__ extout, int outsel) {
    int w = (blockIdx.x * blockDim.x + threadIdx.x) >> 5;
    if (w >= N_NODES) return;
    int lane = threadIdx.x & 31;
    const int c0 = lane * 8;

    int beg = g_rowptr[w];
    int end = g_rowptr[w + 1];
    float a[8];
#pragma unroll
    for (int j = 0; j < 8; j++) a[j] = 0.0f;

    for (int e = beg; e < end; e++) {
        int s = g_csr_src[e];
        float nrm = g_csr_nrm[e];
        const __half2* row = (const __half2*)(g_h + (size_t)s * HID + c0);
#pragma unroll
        for (int j = 0; j < 4; j++) {
            float2 v = __half22float2(row[j]);
            a[2 * j]     = fmaf(nrm, v.x, a[2 * j]);
            a[2 * j + 1] = fmaf(nrm, v.y, a[2 * j + 1]);
        }
    }
    float4 b0 = *(const float4*)(bias + c0);
    float4 b1 = *(const float4*)(bias + c0 + 4);
    a[0] += b0.x; a[1] += b0.y; a[2] += b0.z; a[3] += b0.w;
    a[4] += b1.x; a[5] += b1.y; a[6] += b1.z; a[7] += b1.w;
#pragma unroll
    for (int j = 0; j < 8; j++)
        a[j] = (a[j] > 0.f) ? a[j] : expm1f(a[j]);

    if (outsel) {
        __half2 hv[4];
#pragma unroll
        for (int j = 0; j < 4; j++)
            hv[j] = __floats2half2_rn(a[2 * j], a[2 * j + 1]);
        *(uint4*)(g_x + (size_t)w * HID + c0) = *(uint4*)hv;
    } else {
        float* dst = extout + (size_t)w * HID + c0;
        *(float4*)(dst)     = make_float4(a[0], a[1], a[2], a[3]);
        *(float4*)(dst + 4) = make_float4(a[4], a[5], a[6], a[7]);
    }
}

// ------- CSR gather (64-wide, layer 1): g_aggx = A_norm x  (fp16 out) -------
__global__ __launch_bounds__(256) void gather_x_kernel(const float* __restrict__ x) {
    int w = (blockIdx.x * blockDim.x + threadIdx.x) >> 5;
    if (w >= N_NODES) return;
    int lane = threadIdx.x & 31;

    int beg = g_rowptr[w];
    int end = g_rowptr[w + 1];
    float2 a = make_float2(0.f, 0.f);
    for (int e = beg; e < end; e++) {
        int s = g_csr_src[e];
        float nrm = g_csr_nrm[e];
        float2 v = ((const float2*)(x + (size_t)s * IN_CH))[lane];
        a.x = fmaf(nrm, v.x, a.x);
        a.y = fmaf(nrm, v.y, a.y);
    }
    *(__half2*)(g_aggx + (size_t)w * IN_CH + 2 * lane) = __floats2half2_rn(a.x, a.y);
}

// ---------------- launch -----------------------------------------------------
extern "C" void kernel_launch(void* const* d_in, const int* in_sizes, int n_in,
                              void* d_out, int out_size) {
    const float* x  = (const float*)d_in[0];
    const void*  ei = d_in[1];
    const float* W1 = (const float*)d_in[2];
    const float* b1 = (const float*)d_in[3];
    const float* W2 = (const float*)d_in[4];
    const float* b2 = (const float*)d_in[5];
    const float* W3 = (const float*)d_in[6];
    const float* b3 = (const float*)d_in[7];
    float* out = (float*)d_out;

    const int TPB = 256;
    const int nodeBlocks = (N_NODES + TPB - 1) / TPB;
    const int edgeBlocks = (N_EDGES + TPB - 1) / TPB;
    const int ei2Blocks  = (2 * N_EDGES + TPB - 1) / TPB;
    const int warpNodeBlocks = (N_NODES * 32 + TPB - 1) / TPB;
    dim3 gemmGrid((N_NODES + 127) / 128, 2);      // 782 x 2
    dim3 tblk(32, 8);

    // ---- prep: edges, degree, CSR
    probe_kernel<<<1, 256>>>((const unsigned int*)ei);
    convert_edges_kernel<<<ei2Blocks, TPB>>>(ei);
    zero_idg_kernel<<<nodeBlocks, TPB>>>();
    deg_count_kernel<<<edgeBlocks, TPB>>>();
    dinv_kernel<<<nodeBlocks, TPB>>>();
    scan1_kernel<<<SCAN_BLOCKS, 1024>>>();
    scan2_kernel<<<1, 128>>>();
    scan3_kernel<<<nodeBlocks, TPB>>>();
    csr_fill_kernel<<<edgeBlocks, TPB>>>();

    // ---- layer 1 (aggregate-first): aggx = A_norm x ; x' = elu(aggx W1 + b1)
    gather_x_kernel<<<warpNodeBlocks, TPB>>>(x);
    transT_w_kernel<<<dim3(IN_CH / 32, HID / 32), tblk>>>(W1, IN_CH);
    hgemm_kernel<<<gemmGrid, 256>>>(1, b1, 2, IN_CH, 1);

    // ---- layer 2: h = x' W2 ; x'' = elu(A_norm h + b2)
    transT_w_kernel<<<dim3(HID / 32, HID / 32), tblk>>>(W2, HID);
    hgemm_kernel<<<gemmGrid, 256>>>(2, nullptr, 1, HID, 0);
    gather_h_kernel<<<warpNodeBlocks, TPB>>>(b2, nullptr, 1);

    // ---- layer 3: h = x'' W3 ; out = elu(A_norm h + b3)
    transT_w_kernel<<<dim3(HID / 32, HID / 32), tblk>>>(W3, HID);
    hgemm_kernel<<<gemmGrid, 256>>>(2, nullptr, 1, HID, 0);
    gather_h_kernel<<<warpNodeBlocks, TPB>>>(b3, out, 0);
}

// round 7
// speedup vs baseline: 4.4985x; 1.0423x over previous
#include <cuda_runtime.h>
#include <cuda_fp16.h>
#include <math.h>
#include <stdint.h>

#define N_NODES 100000
#define N_EDGES 600000
#define HID 256
#define IN_CH 64
#define SCAN_BLOCKS ((N_NODES + 1023) / 1024)   // 98

// ---------------- scratch (device globals; no allocation allowed) ----------
__device__ __half g_h   [(size_t)N_NODES * HID];   // post-GEMM features (fp16)
__device__ __half g_x   [(size_t)N_NODES * HID];   // layer activations (fp16)
__device__ __half g_aggx[(size_t)N_NODES * IN_CH]; // layer-1 aggregated input
__device__ __half g_wT  [HID * HID];               // W^T [N][K] fp16
__device__ float  g_dinv[N_NODES];
__device__ int    g_idg [N_NODES];
__device__ int    g_rowptr[N_NODES + 1];
__device__ int    g_cursor[N_NODES];
__device__ int    g_bsum[SCAN_BLOCKS];
__device__ int    g_boff[SCAN_BLOCKS];
__device__ int    g_csr_src[N_EDGES];
__device__ float  g_csr_nrm[N_EDGES];
__device__ int    g_is64;

// ---------------- helpers ----------------------------------------------------
__device__ __forceinline__ void cp16(const void* dstp, const void* src, int srcsz) {
    uint32_t d = (uint32_t)__cvta_generic_to_shared(dstp);
    asm volatile("cp.async.ca.shared.global [%0], [%1], 16, %2;"
                 :: "r"(d), "l"(src), "r"(srcsz));
}

__device__ __forceinline__ void mma_f16(float c[4], const uint32_t a[4],
                                        uint32_t b0, uint32_t b1) {
    asm volatile(
        "mma.sync.aligned.m16n8k16.row.col.f32.f16.f16.f32 "
        "{%0,%1,%2,%3}, {%4,%5,%6,%7}, {%8,%9}, {%0,%1,%2,%3};"
        : "+f"(c[0]), "+f"(c[1]), "+f"(c[2]), "+f"(c[3])
        : "r"(a[0]), "r"(a[1]), "r"(a[2]), "r"(a[3]), "r"(b0), "r"(b1));
}

__device__ __forceinline__ int edge_at(const void* ei, int idx) {
    return g_is64 ? (int)((const long long*)ei)[idx] : ((const int*)ei)[idx];
}

// ---------------- dtype probe -------------------------------------------------
__global__ void probe_kernel(const unsigned int* __restrict__ words) {
    __shared__ int nz;
    if (threadIdx.x == 0) nz = 0;
    __syncthreads();
    int local = 0;
    for (int i = threadIdx.x; i < 1024; i += blockDim.x)
        if (words[2 * i + 1] != 0u) local = 1;
    if (local) atomicOr(&nz, 1);
    __syncthreads();
    if (threadIdx.x == 0) g_is64 = (nz == 0) ? 1 : 0;
}

// ---------------- degree -----------------------------------------------------
__global__ void zero_idg_kernel() {
    int i = blockIdx.x * blockDim.x + threadIdx.x;
    if (i < N_NODES) g_idg[i] = 0;
}

__global__ void deg_count_kernel(const void* __restrict__ ei) {
    int e = blockIdx.x * blockDim.x + threadIdx.x;
    if (e < N_EDGES) atomicAdd(&g_idg[edge_at(ei, N_EDGES + e)], 1);
}

// ---------------- CSR build (scan1 also emits dinv) --------------------------
__global__ __launch_bounds__(1024) void scan1_kernel() {
    __shared__ int sh[1024];
    int i = blockIdx.x * 1024 + threadIdx.x;
    int v = (i < N_NODES) ? g_idg[i] : 0;
    sh[threadIdx.x] = v;
    __syncthreads();
#pragma unroll
    for (int off = 1; off < 1024; off <<= 1) {
        int t = (threadIdx.x >= off) ? sh[threadIdx.x - off] : 0;
        __syncthreads();
        sh[threadIdx.x] += t;
        __syncthreads();
    }
    if (i < N_NODES) {
        g_rowptr[i] = sh[threadIdx.x] - v;
        g_dinv[i] = (v > 0) ? rsqrtf((float)v) : 0.0f;
    }
    if (threadIdx.x == 1023) g_bsum[blockIdx.x] = sh[1023];
}

__global__ void scan2_kernel() {
    __shared__ int sh[SCAN_BLOCKS];
    int tid = threadIdx.x;
    if (tid < SCAN_BLOCKS) sh[tid] = g_bsum[tid];
    __syncthreads();
    if (tid == 0) {
        int acc = 0;
        for (int b = 0; b < SCAN_BLOCKS; b++) { int t = sh[b]; sh[b] = acc; acc += t; }
    }
    __syncthreads();
    if (tid < SCAN_BLOCKS) g_boff[tid] = sh[tid];
}

__global__ void scan3_kernel() {
    int i = blockIdx.x * blockDim.x + threadIdx.x;
    if (i < N_NODES) {
        int r = g_rowptr[i] + g_boff[i >> 10];
        g_rowptr[i] = r;
        g_cursor[i] = r;
    }
    if (i == 0) g_rowptr[N_NODES] = N_EDGES;
}

__global__ void csr_fill_kernel(const void* __restrict__ ei) {
    int e = blockIdx.x * blockDim.x + threadIdx.x;
    if (e >= N_EDGES) return;
    int s = edge_at(ei, e);
    int d = edge_at(ei, N_EDGES + e);
    int pos = atomicAdd(&g_cursor[d], 1);
    g_csr_src[pos] = s;
    g_csr_nrm[pos] = g_dinv[s] * g_dinv[d];
}

// -------- weight transpose + fp16 convert: g_wT[n][k] = h(W[k][n]) ----------
__global__ void transT_w_kernel(const float* __restrict__ W, int K) {
    __shared__ float t[32][33];
    int kb = blockIdx.x * 32, nb = blockIdx.y * 32;
    int tx = threadIdx.x, ty = threadIdx.y;     // block 32x8
#pragma unroll
    for (int j = 0; j < 32; j += 8)
        t[ty + j][tx] = W[(size_t)(kb + ty + j) * HID + nb + tx];
    __syncthreads();
#pragma unroll
    for (int j = 0; j < 32; j += 8)
        g_wT[(size_t)(nb + ty + j) * K + kb + tx] = __float2half_rn(t[tx][ty + j]);
}

// ---------------- fp16 tensor GEMM: C[M,256] = A[M,K] @ W[K,256] -------------
// BM=128, BN=128 (gridDim.y=2), BK=32 halves, 3-stage cp.async pipeline
// with ONE __syncthreads per iteration.  8 warps: warpM=warp&3, warpN=warp>>2;
// warp tile 32x64: 2 m-atoms x 8 n-atoms of m16n8k16.
// asel: 1 = g_aggx (K=64), 2 = g_x.  csel: 1 = g_h, 2 = g_x.
#define HSTR 40   // halves per smem row (80B, 16B-aligned, conflict-free)
#define GEMM_SMEM (6 * 128 * HSTR * 2)   // 3 stages x (A+B) = 61440 B
__global__ __launch_bounds__(256, 2) void hgemm_kernel(
        int asel, const float* __restrict__ bias, int csel, int K, int do_act) {
    const __half* __restrict__ A = (asel == 1) ? g_aggx : g_x;
    __half* __restrict__ C = (csel == 1) ? g_h : g_x;
    const int M = N_NODES;

    extern __shared__ __align__(16) __half smem[];
    __half (*As)[128][HSTR] = (__half(*)[128][HSTR])smem;                  // [3]
    __half (*Bs)[128][HSTR] = (__half(*)[128][HSTR])(smem + 3 * 128 * HSTR);

    const int tid  = threadIdx.x;
    const int lane = tid & 31;
    const int warp = tid >> 5;
    const int warpM = warp & 3;
    const int warpN = warp >> 2;
    const int gid = lane >> 2;
    const int lc  = lane & 3;
    const int blockM = blockIdx.x * 128;
    const int blockN = blockIdx.y * 128;

    float acc[2][8][4];
#pragma unroll
    for (int i = 0; i < 2; i++)
#pragma unroll
        for (int j = 0; j < 8; j++)
#pragma unroll
            for (int v = 0; v < 4; v++) acc[i][j][v] = 0.0f;

    const int nk = K / 32;

    auto load_stage = [&](int buf, int k0) {
#pragma unroll
        for (int i = 0; i < 2; i++) {
            int idx = tid + i * 256;
            int r = idx >> 2, seg = (idx & 3) * 8;
            int grow = blockM + r;
            const __half* asrc = A + (size_t)((grow < M) ? grow : M - 1) * K + k0 + seg;
            cp16(&As[buf][r][seg], asrc, (grow < M) ? 16 : 0);
            const __half* bsrc = g_wT + (size_t)(blockN + r) * K + k0 + seg;
            cp16(&Bs[buf][r][seg], bsrc, 16);
        }
    };

    // prologue: stages 0 and 1
    load_stage(0, 0);
    asm volatile("cp.async.commit_group;" ::: "memory");
    if (nk > 1) load_stage(1, 32);
    asm volatile("cp.async.commit_group;" ::: "memory");

    int buf = 0;
    for (int it = 0; it < nk; it++) {
        asm volatile("cp.async.wait_group 1;" ::: "memory");
        __syncthreads();

#pragma unroll
        for (int kk = 0; kk < 2; kk++) {
            const int kb = kk * 16 + 2 * lc;
            uint32_t a[2][4];
#pragma unroll
            for (int i = 0; i < 2; i++) {
                int r = warpM * 32 + i * 16 + gid;
                a[i][0] = *(const uint32_t*)&As[buf][r][kb];
                a[i][1] = *(const uint32_t*)&As[buf][r + 8][kb];
                a[i][2] = *(const uint32_t*)&As[buf][r][kb + 8];
                a[i][3] = *(const uint32_t*)&As[buf][r + 8][kb + 8];
            }
#pragma unroll
            for (int j = 0; j < 8; j++) {
                int cc = warpN * 64 + j * 8 + gid;
                uint32_t b0 = *(const uint32_t*)&Bs[buf][cc][kb];
                uint32_t b1 = *(const uint32_t*)&Bs[buf][cc][kb + 8];
                mma_f16(acc[0][j], a[0], b0, b1);
                mma_f16(acc[1][j], a[1], b0, b1);
            }
        }

        // prefetch stage it+2 into buffer (it+2)%3 — its previous occupant
        // (stage it-1) was fully consumed before this iteration's barrier.
        if (it + 2 < nk) {
            int nbuf = buf + 2; if (nbuf >= 3) nbuf -= 3;
            load_stage(nbuf, (it + 2) * 32);
        }
        asm volatile("cp.async.commit_group;" ::: "memory");

        if (++buf == 3) buf = 0;
    }

    // ---- epilogue: fp32 bias+ELU, round-to-fp16 store
#pragma unroll
    for (int i = 0; i < 2; i++) {
#pragma unroll
        for (int j = 0; j < 8; j++) {
            int col = blockN + warpN * 64 + j * 8 + 2 * lc;
            int row0 = blockM + warpM * 32 + i * 16 + gid;
            int row1 = row0 + 8;
            float v0 = acc[i][j][0], v1 = acc[i][j][1];
            float v2 = acc[i][j][2], v3 = acc[i][j][3];
            if (do_act) {
                float bb0 = bias[col], bb1 = bias[col + 1];
                v0 += bb0; v1 += bb1; v2 += bb0; v3 += bb1;
                v0 = (v0 > 0.f) ? v0 : expm1f(v0);
                v1 = (v1 > 0.f) ? v1 : expm1f(v1);
                v2 = (v2 > 0.f) ? v2 : expm1f(v2);
                v3 = (v3 > 0.f) ? v3 : expm1f(v3);
            }
            if (row0 < M)
                *(__half2*)(C + (size_t)row0 * HID + col) = __floats2half2_rn(v0, v1);
            if (row1 < M)
                *(__half2*)(C + (size_t)row1 * HID + col) = __floats2half2_rn(v2, v3);
        }
    }
}

// ------- CSR gather (256-wide fp16 rows): elu(sum nrm*h[src] + bias) --------
__global__ __launch_bounds__(256) void gather_h_kernel(
        const float* __restrict__ bias, float* __restrict__ extout, int outsel) {
    int w = (blockIdx.x * blockDim.x + threadIdx.x) >> 5;
    if (w >= N_NODES) return;
    int lane = threadIdx.x & 31;
    const int c0 = lane * 8;

    int beg = g_rowptr[w];
    int end = g_rowptr[w + 1];
    float a[8];
#pragma unroll
    for (int j = 0; j < 8; j++) a[j] = 0.0f;

    for (int e = beg; e < end; e++) {
        int s = g_csr_src[e];
        float nrm = g_csr_nrm[e];
        const __half2* row = (const __half2*)(g_h + (size_t)s * HID + c0);
#pragma unroll
        for (int j = 0; j < 4; j++) {
            float2 v = __half22float2(row[j]);
            a[2 * j]     = fmaf(nrm, v.x, a[2 * j]);
            a[2 * j + 1] = fmaf(nrm, v.y, a[2 * j + 1]);
        }
    }
    float4 b0 = *(const float4*)(bias + c0);
    float4 b1 = *(const float4*)(bias + c0 + 4);
    a[0] += b0.x; a[1] += b0.y; a[2] += b0.z; a[3] += b0.w;
    a[4] += b1.x; a[5] += b1.y; a[6] += b1.z; a[7] += b1.w;
#pragma unroll
    for (int j = 0; j < 8; j++)
        a[j] = (a[j] > 0.f) ? a[j] : expm1f(a[j]);

    if (outsel) {
        __half2 hv[4];
#pragma unroll
        for (int j = 0; j < 4; j++)
            hv[j] = __floats2half2_rn(a[2 * j], a[2 * j + 1]);
        *(uint4*)(g_x + (size_t)w * HID + c0) = *(uint4*)hv;
    } else {
        float* dst = extout + (size_t)w * HID + c0;
        *(float4*)(dst)     = make_float4(a[0], a[1], a[2], a[3]);
        *(float4*)(dst + 4) = make_float4(a[4], a[5], a[6], a[7]);
    }
}

// ------- CSR gather (64-wide, layer 1): g_aggx = A_norm x  (fp16 out) -------
__global__ __launch_bounds__(256) void gather_x_kernel(const float* __restrict__ x) {
    int w = (blockIdx.x * blockDim.x + threadIdx.x) >> 5;
    if (w >= N_NODES) return;
    int lane = threadIdx.x & 31;

    int beg = g_rowptr[w];
    int end = g_rowptr[w + 1];
    float2 a = make_float2(0.f, 0.f);
    for (int e = beg; e < end; e++) {
        int s = g_csr_src[e];
        float nrm = g_csr_nrm[e];
        float2 v = ((const float2*)(x + (size_t)s * IN_CH))[lane];
        a.x = fmaf(nrm, v.x, a.x);
        a.y = fmaf(nrm, v.y, a.y);
    }
    *(__half2*)(g_aggx + (size_t)w * IN_CH + 2 * lane) = __floats2half2_rn(a.x, a.y);
}

// ---------------- launch -----------------------------------------------------
extern "C" void kernel_launch(void* const* d_in, const int* in_sizes, int n_in,
                              void* d_out, int out_size) {
    const float* x  = (const float*)d_in[0];
    const void*  ei = d_in[1];
    const float* W1 = (const float*)d_in[2];
    const float* b1 = (const float*)d_in[3];
    const float* W2 = (const float*)d_in[4];
    const float* b2 = (const float*)d_in[5];
    const float* W3 = (const float*)d_in[6];
    const float* b3 = (const float*)d_in[7];
    float* out = (float*)d_out;

    // idempotent attribute set — not a stream op, capture-safe
    cudaFuncSetAttribute(hgemm_kernel,
                         cudaFuncAttributeMaxDynamicSharedMemorySize, GEMM_SMEM);

    const int TPB = 256;
    const int nodeBlocks = (N_NODES + TPB - 1) / TPB;
    const int edgeBlocks = (N_EDGES + TPB - 1) / TPB;
    const int warpNodeBlocks = (N_NODES * 32 + TPB - 1) / TPB;
    dim3 gemmGrid((N_NODES + 127) / 128, 2);      // 782 x 2
    dim3 tblk(32, 8);

    // ---- prep: probe, degree, CSR (dinv fused into scan1)
    probe_kernel<<<1, 256>>>((const unsigned int*)ei);
    zero_idg_kernel<<<nodeBlocks, TPB>>>();
    deg_count_kernel<<<edgeBlocks, TPB>>>(ei);
    scan1_kernel<<<SCAN_BLOCKS, 1024>>>();
    scan2_kernel<<<1, 128>>>();
    scan3_kernel<<<nodeBlocks, TPB>>>();
    csr_fill_kernel<<<edgeBlocks, TPB>>>(ei);

    // ---- layer 1 (aggregate-first): aggx = A_norm x ; x' = elu(aggx W1 + b1)
    gather_x_kernel<<<warpNodeBlocks, TPB>>>(x);
    transT_w_kernel<<<dim3(IN_CH / 32, HID / 32), tblk>>>(W1, IN_CH);
    hgemm_kernel<<<gemmGrid, 256, GEMM_SMEM>>>(1, b1, 2, IN_CH, 1);

    // ---- layer 2: h = x' W2 ; x'' = elu(A_norm h + b2)
    transT_w_kernel<<<dim3(HID / 32, HID / 32), tblk>>>(W2, HID);
    hgemm_kernel<<<gemmGrid, 256, GEMM_SMEM>>>(2, nullptr, 1, HID, 0);
    gather_h_kernel<<<warpNodeBlocks, TPB>>>(b2, nullptr, 1);

    // ---- layer 3: h = x'' W3 ; out = elu(A_norm h + b3)
    transT_w_kernel<<<dim3(HID / 32, HID / 32), tblk>>>(W3, HID);
    hgemm_kernel<<<gemmGrid, 256, GEMM_SMEM>>>(2, nullptr, 1, HID, 0);
    gather_h_kernel<<<warpNodeBlocks, TPB>>>(b3, out, 0);
}